// round 14
// baseline (speedup 1.0000x reference)
#include <cuda_runtime.h>
#include <cuda_bf16.h>
#include <cstdint>

typedef __nv_bfloat16 bf16;

#define TT 1024
#define BB 64
#define WW 512
#define W3 1536
#define GRID 128
#define NTH 512

// smem layout (bytes)
#define SM_RM   0                    // float[64]
#define SM_BIA  256                  // float[24]
#define SM_BHN  384                  // float[8]
#define SM_BLFR 1024                 // B-lo fragments: 8ks*8j*3nt*256B = 49152
#define SM_A    50176                // A ring: 8 ks * 3 bufs * 5120B = 122880
#define SM_PART 173056               // 16 warps * 32 * 24 fp32 = 49152
#define SM_WSTG SM_A                 // init-only weight staging (110592B, inside A)
#define SMEM_BYTES 222208

__device__ __align__(128) bf16 g_xHi[TT][BB][WW];
__device__ __align__(128) bf16 g_xLo[TT][BB][WW];
__device__ __align__(128) bf16 g_hHi[2][2][BB][WW];   // [layer][buf][b][w]
__device__ __align__(128) bf16 g_hLo[2][2][BB][WW];
__device__ __align__(128) float g_hF[2][2][BB][WW];
__device__ unsigned g_cnt = 0;
__device__ volatile unsigned g_gen = 0;
__device__ int g_reset_mode = 0;

__device__ __forceinline__ float reset_mask(const void* r, int mode, int idx)
{
    if (mode == 1) return ((const int*)r)[idx] != 0 ? 0.0f : 1.0f;
    if (mode == 2) return ((const float*)r)[idx] != 0.0f ? 0.0f : 1.0f;
    return ((const unsigned char*)r)[idx] != 0 ? 0.0f : 1.0f;
}

// prep: split ins into bf16 hi/lo (blocks 0..32767); block 32768 sniffs resets
__global__ void prep_kernel(const float* __restrict__ ins,
                            const unsigned* __restrict__ resets)
{
    if (blockIdx.x == 32768) {
        __shared__ unsigned red[256];
        unsigned m = 0;
        for (int i = threadIdx.x; i < (TT * BB) / 4; i += 256) m = max(m, resets[i]);
        red[threadIdx.x] = m;
        __syncthreads();
        for (int s = 128; s > 0; s >>= 1) {
            if (threadIdx.x < s) red[threadIdx.x] = max(red[threadIdx.x], red[threadIdx.x + s]);
            __syncthreads();
        }
        if (threadIdx.x == 0) {
            unsigned mx = red[0];
            g_reset_mode = (mx <= 1u) ? 1 : (mx >= 0x10000000u ? 2 : 0);
        }
        return;
    }
    size_t i = ((size_t)blockIdx.x * 256 + threadIdx.x) * 4;
    float4 v = *(const float4*)(ins + i);
    const float f[4] = {v.x, v.y, v.z, v.w};
    bf16* xh = &g_xHi[0][0][0];
    bf16* xl = &g_xLo[0][0][0];
#pragma unroll
    for (int j = 0; j < 4; ++j) {
        bf16 h = __float2bfloat16(f[j]);
        xh[i + j] = h;
        xl[i + j] = __float2bfloat16(f[j] - __bfloat162float(h));
    }
}

__device__ __forceinline__ uint32_t smem_u32(const void* p)
{
    uint32_t a;
    asm("{ .reg .u64 t; cvta.to.shared.u64 t, %1; cvt.u32.u64 %0, t; }" : "=r"(a) : "l"(p));
    return a;
}

#define LDSM4(d, addr) asm volatile( \
    "ldmatrix.sync.aligned.m8n8.x4.shared.b16 {%0,%1,%2,%3},[%4];" \
    : "=r"((d)[0]), "=r"((d)[1]), "=r"((d)[2]), "=r"((d)[3]) : "r"(addr))
#define LDSM2(d, addr) asm volatile( \
    "ldmatrix.sync.aligned.m8n8.x2.shared.b16 {%0,%1},[%2];" \
    : "=r"((d)[0]), "=r"((d)[1]) : "r"(addr))
#define MMA(acc, A, B) asm volatile( \
    "mma.sync.aligned.m16n8k16.row.col.f32.bf16.bf16.f32 " \
    "{%0,%1,%2,%3},{%4,%5,%6,%7},{%8,%9},{%0,%1,%2,%3};" \
    : "+f"((acc)[0]), "+f"((acc)[1]), "+f"((acc)[2]), "+f"((acc)[3]) \
    : "r"((A)[0]), "r"((A)[1]), "r"((A)[2]), "r"((A)[3]), "r"((B)[0]), "r"((B)[1]))

// stage this warp's 32 rows of one 16-k sub-chunk (hi+lo) into the shared ring
__device__ __forceinline__ void stage_sub(const bf16* sH, const bf16* sL, int kk,
                                          uint32_t db, int row)
{
    uint32_t d = db + row * 80;
    const bf16* ph = sH + row * 512 + kk;
    const bf16* pl = sL + row * 512 + kk;
    asm volatile("cp.async.cg.shared.global [%0],[%1],16;\n\t"
                 "cp.async.cg.shared.global [%2],[%3],16;\n\t"
                 "cp.async.cg.shared.global [%4],[%5],16;\n\t"
                 "cp.async.cg.shared.global [%6],[%7],16;\n\t"
                 "cp.async.commit_group;"
                 :: "r"(d), "l"(ph), "r"(d + 16), "l"(ph + 8),
                    "r"(d + 32), "l"(pl), "r"(d + 48), "l"(pl + 8) : "memory");
}

__global__ void __launch_bounds__(NTH, 1)
gru_scan_kernel(const void* __restrict__ resets,
                const float* __restrict__ Wi, const float* __restrict__ bi,
                const float* __restrict__ Wh, const float* __restrict__ bhn,
                float* __restrict__ out)
{
    extern __shared__ char smem[];
    const uint32_t sbase = smem_u32(smem);
    float* rm   = (float*)(smem + SM_RM);
    float* bia  = (float*)(smem + SM_BIA);
    float* bhna = (float*)(smem + SM_BHN);
    float* part = (float*)(smem + SM_PART);

    const int tid = threadIdx.x, lane = tid & 31, warp = tid >> 5;  // 0..15
    const int ks = warp >> 1, mhalf = warp & 1;       // K-slice, M-half
    const int cta = blockIdx.x, group = cta >> 6, lyr = group ? 0 : 1;
    const int gwBase = (cta & 63) * 8;
    const int rmode = g_reset_mode;
    const int r8 = lane & 7, g4 = lane >> 3;

    // ---- init: weights (bf16 hi/lo) into staging smem: rows (k>>6)*24+c x 144B ----
    const float* WiL = Wi + (size_t)lyr * WW * W3;
    const float* WhL = Wh + (size_t)lyr * WW * W3;
    for (int idx = tid; idx < 24 * 1024; idx += NTH) {
        int c = idx % 24, k = idx / 24;
        int gc = gwBase + (c & 7) + (c >> 3) * WW;
        float v = (k < WW) ? WiL[(size_t)k * W3 + gc] : WhL[(size_t)(k - WW) * W3 + gc];
        bf16 h = __float2bfloat16(v);
        bf16 l = __float2bfloat16(v - __bfloat162float(h));
        int off = ((k >> 6) * 24 + c) * 144 + (k & 63) * 2;
        *(bf16*)(smem + SM_WSTG + off) = h;
        *(bf16*)(smem + SM_WSTG + 55296 + off) = l;
    }
    if (tid < 24) bia[tid] = bi[lyr * W3 + (tid >> 3) * WW + gwBase + (tid & 7)];
    if (tid < 8)  bhna[tid] = bhn[lyr * WW + gwBase + tid];
    unsigned gen = 0;
    if (tid == 0) gen = g_gen;
    __syncthreads();

    // ---- B-hi fragments into registers; B-lo fragments into smem frag array ----
    uint32_t bh[3][8][2];
#pragma unroll
    for (int nt = 0; nt < 3; ++nt)
#pragma unroll
        for (int j = 0; j < 8; ++j) {
            int kc = ks * 2 + (j >> 2), q = j & 3;
            uint32_t ba = sbase + SM_WSTG + kc * 3456 +
                          (nt * 8 + r8) * 144 + (g4 & 1) * 16 + q * 32;
            LDSM2(bh[nt][j], ba);
            if (mhalf == 0) {
                uint32_t bl[2];
                LDSM2(bl, ba + 55296);
                *(uint2*)(smem + SM_BLFR + ((ks * 8 + j) * 3 + nt) * 256 + lane * 8) =
                    make_uint2(bl[0], bl[1]);
            }
        }
    __syncthreads();   // staging area now reusable as A ring / part

    const uint32_t ring = sbase + SM_A + ks * 15360;          // 3 bufs x 5120
    const uint32_t aoff = (mhalf * 32) * 80 + ((g4 & 1) * 8 + r8) * 80 + (g4 >> 1) * 16;
    const uint32_t blbase = sbase + SM_BLFR + ks * 8 * 3 * 256 + lane * 8;
    const int k0 = (ks & 3) * 128;                            // k base within half
    const int srow = mhalf * 32 + lane;                       // staging row (own rows)

    float* out_carry = out;
    float* out_ys    = out + 2 * BB * WW;

#pragma unroll 1
    for (int p = 0; p <= TT; ++p) {
        const bool active = group ? (p < TT) : (p >= 1);
        const int t = group ? p : (p - 1);
        const int hbuf = (p - 1) & 1;
        if (active) {
            const bool zeroH = group ? (p == 0) : (p == 1);
            const bf16* iHi = group ? &g_xHi[t][0][0] : &g_hHi[0][hbuf][0][0];
            const bf16* iLo = group ? &g_xLo[t][0][0] : &g_hLo[0][hbuf][0][0];
            const bf16* sH = (ks < 4) ? iHi : &g_hHi[lyr][hbuf][0][0];
            const bf16* sL = (ks < 4) ? iLo : &g_hLo[lyr][hbuf][0][0];

            if (tid < BB)
                rm[tid] = zeroH ? 0.0f : reset_mask(resets, rmode, t * BB + tid);

            float acc[2][3][4];
#pragma unroll
            for (int mt = 0; mt < 2; ++mt)
#pragma unroll
                for (int nt = 0; nt < 3; ++nt)
#pragma unroll
                    for (int q = 0; q < 4; ++q) acc[mt][nt][q] = 0.0f;

            stage_sub(sH, sL, k0 + 0 * 16, ring + 0 * 5120, srow);
            stage_sub(sH, sL, k0 + 1 * 16, ring + 1 * 5120, srow);
            stage_sub(sH, sL, k0 + 2 * 16, ring + 2 * 5120, srow);

#pragma unroll
            for (int s = 0; s < 8; ++s) {
                if (s < 6)       asm volatile("cp.async.wait_group 2;" ::: "memory");
                else if (s == 6) asm volatile("cp.async.wait_group 1;" ::: "memory");
                else             asm volatile("cp.async.wait_group 0;" ::: "memory");
                __syncwarp();
                const uint32_t ab = ring + (s % 3) * 5120 + aoff;
                uint32_t bl[3][2];
#pragma unroll
                for (int nt = 0; nt < 3; ++nt) {
                    uint2 v = *(const uint2*)(uintptr_t)(blbase + (s * 3 + nt) * 256 -
                                                         sbase + (uintptr_t)smem);
                    bl[nt][0] = v.x; bl[nt][1] = v.y;
                }
#pragma unroll
                for (int mt = 0; mt < 2; ++mt) {
                    uint32_t ah[4], al[4];
                    LDSM4(ah, ab + mt * 1280);
                    LDSM4(al, ab + mt * 1280 + 32);
#pragma unroll
                    for (int nt = 0; nt < 3; ++nt) {
                        MMA(acc[mt][nt], ah, bh[nt][s]);
                        MMA(acc[mt][nt], ah, bl[nt]);
                        MMA(acc[mt][nt], al, bh[nt][s]);
                    }
                }
                if (s < 5)
                    stage_sub(sH, sL, k0 + (s + 3) * 16, ring + (s % 3) * 5120, srow);
            }

            // dump this warp's 32x24 partial tile
            {
                float* prt = part + warp * 768;
                const int dr = lane >> 2, dc = (lane & 3) * 2;
#pragma unroll
                for (int mt = 0; mt < 2; ++mt)
#pragma unroll
                    for (int nt = 0; nt < 3; ++nt) {
                        int b0 = (mt * 16 + dr) * 24 + nt * 8 + dc;
                        *(float2*)(prt + b0)       = make_float2(acc[mt][nt][0], acc[mt][nt][1]);
                        *(float2*)(prt + b0 + 192) = make_float2(acc[mt][nt][2], acc[mt][nt][3]);
                    }
            }
        }

        __syncthreads();

        if (active) {
            const float* hF = group ? &g_hF[0][hbuf][0][0] + 0 : &g_hF[1][hbuf][0][0];
            const float* hFs = &g_hF[lyr][hbuf][0][0];
            (void)hF;
            const int pb = p & 1;
            const int b = tid >> 3, ttl = tid & 7;
            const float m = rm[b];
            const int mh = b >> 5, lr = b & 31;
            float si[3], sh2[3];
#pragma unroll
            for (int g = 0; g < 3; ++g) {
                const int c = g * 8 + ttl;
                float a0 = 0.0f, a1 = 0.0f;
#pragma unroll
                for (int k8 = 0; k8 < 4; ++k8) {
                    a0 += part[(k8 * 2 + mh) * 768 + lr * 24 + c];
                    a1 += part[((k8 + 4) * 2 + mh) * 768 + lr * 24 + c];
                }
                si[g] = a0; sh2[g] = a1;
            }
            const float r = 1.0f / (1.0f + __expf(-(bia[ttl] + si[0] + m * sh2[0])));
            const float z = 1.0f / (1.0f + __expf(-(bia[8 + ttl] + si[1] + m * sh2[1])));
            const float n = tanhf(bia[16 + ttl] + si[2] + r * (m * sh2[2] + bhna[ttl]));
            const int w = gwBase + ttl;
            const float hp = m * __ldcg(hFs + b * 512 + w);
            const float h = (1.0f - z) * n + z * hp;
            bf16 hh = __float2bfloat16(h);
            g_hF [lyr][pb][b][w] = h;
            g_hHi[lyr][pb][b][w] = hh;
            g_hLo[lyr][pb][b][w] = __float2bfloat16(h - __bfloat162float(hh));
            if (group == 0) {
                out_ys[(size_t)t * BB * WW + b * WW + w] = h;
                if (p == TT) out_carry[BB * WW + b * WW + w] = h;
            } else if (p == TT - 1) {
                out_carry[b * WW + w] = h;
            }
        }

        // lockstep grid barrier
        __syncthreads();
        if (tid == 0) {
            __threadfence();
            unsigned a = atomicAdd(&g_cnt, 1);
            gen += 1;
            if (a == GRID - 1) {
                g_cnt = 0;
                __threadfence();
                g_gen = gen;
            } else {
                while (g_gen < gen) { __nanosleep(20); }
                __threadfence();
            }
        }
        __syncthreads();
    }
}

extern "C" void kernel_launch(void* const* d_in, const int* in_sizes, int n_in,
                              void* d_out, int out_size)
{
    const float* ins    = (const float*)d_in[0];
    const void*  resets = (const void*)d_in[1];
    const float* Wi     = (const float*)d_in[2];
    const float* bi     = (const float*)d_in[3];
    const float* Wh     = (const float*)d_in[4];
    const float* bhn    = (const float*)d_in[5];
    float*       out    = (float*)d_out;

    prep_kernel<<<32769, 256>>>(ins, (const unsigned*)resets);

    cudaFuncSetAttribute(gru_scan_kernel,
                         cudaFuncAttributeMaxDynamicSharedMemorySize, SMEM_BYTES);
    gru_scan_kernel<<<GRID, NTH, SMEM_BYTES>>>(resets, Wi, bi, Wh, bhn, out);
}

// round 15
// speedup vs baseline: 1.2366x; 1.2366x over previous
#include <cuda_runtime.h>
#include <cuda_bf16.h>
#include <cstdint>

typedef __nv_bfloat16 bf16;

#define TT 1024
#define BB 64
#define WW 512
#define W3 1536
#define GRID 128
#define NTH 256

// smem layout (bytes)
#define SM_RM   0
#define SM_BIA  256
#define SM_BHN  384
#define SM_WSTG 1024                 // weights staging hi(55296)+lo(55296), init-only
#define SM_PART 1024                 // 8 x 64 x 24 fp32 = 49152 -> ends 50176
#define SM_A    50176                // 8 warps x 4 bufs x 5120B = 163840
#define SMEM_BYTES 214016

__device__ __align__(128) bf16 g_xHi[TT][BB][WW];
__device__ __align__(128) bf16 g_xLo[TT][BB][WW];
__device__ __align__(128) bf16 g_hHi[2][2][BB][WW];   // [layer][buf][b][w]
__device__ __align__(128) bf16 g_hLo[2][2][BB][WW];
__device__ __align__(128) float g_hF[2][2][BB][WW];
__device__ unsigned g_cnt = 0;
__device__ volatile unsigned g_gen = 0;
__device__ int g_reset_mode = 0;

__device__ __forceinline__ float reset_mask(const void* r, int mode, int idx)
{
    if (mode == 1) return ((const int*)r)[idx] != 0 ? 0.0f : 1.0f;
    if (mode == 2) return ((const float*)r)[idx] != 0.0f ? 0.0f : 1.0f;
    return ((const unsigned char*)r)[idx] != 0 ? 0.0f : 1.0f;
}

// prep: split ins into bf16 hi/lo (blocks 0..32767); block 32768 sniffs resets
__global__ void prep_kernel(const float* __restrict__ ins,
                            const unsigned* __restrict__ resets)
{
    if (blockIdx.x == 32768) {
        __shared__ unsigned red[256];
        unsigned m = 0;
        for (int i = threadIdx.x; i < (TT * BB) / 4; i += 256) m = max(m, resets[i]);
        red[threadIdx.x] = m;
        __syncthreads();
        for (int s = 128; s > 0; s >>= 1) {
            if (threadIdx.x < s) red[threadIdx.x] = max(red[threadIdx.x], red[threadIdx.x + s]);
            __syncthreads();
        }
        if (threadIdx.x == 0) {
            unsigned mx = red[0];
            g_reset_mode = (mx <= 1u) ? 1 : (mx >= 0x10000000u ? 2 : 0);
        }
        return;
    }
    size_t i = ((size_t)blockIdx.x * 256 + threadIdx.x) * 4;
    float4 v = *(const float4*)(ins + i);
    const float f[4] = {v.x, v.y, v.z, v.w};
    bf16* xh = &g_xHi[0][0][0];
    bf16* xl = &g_xLo[0][0][0];
#pragma unroll
    for (int j = 0; j < 4; ++j) {
        bf16 h = __float2bfloat16(f[j]);
        xh[i + j] = h;
        xl[i + j] = __float2bfloat16(f[j] - __bfloat162float(h));
    }
}

__device__ __forceinline__ uint32_t smem_u32(const void* p)
{
    uint32_t a;
    asm("{ .reg .u64 t; cvta.to.shared.u64 t, %1; cvt.u32.u64 %0, t; }" : "=r"(a) : "l"(p));
    return a;
}

#define LDSM4(d, addr) asm volatile( \
    "ldmatrix.sync.aligned.m8n8.x4.shared.b16 {%0,%1,%2,%3},[%4];" \
    : "=r"((d)[0]), "=r"((d)[1]), "=r"((d)[2]), "=r"((d)[3]) : "r"(addr))
#define LDSM2(d, addr) asm volatile( \
    "ldmatrix.sync.aligned.m8n8.x2.shared.b16 {%0,%1},[%2];" \
    : "=r"((d)[0]), "=r"((d)[1]) : "r"(addr))
#define MMA(acc, A, B) asm volatile( \
    "mma.sync.aligned.m16n8k16.row.col.f32.bf16.bf16.f32 " \
    "{%0,%1,%2,%3},{%4,%5,%6,%7},{%8,%9},{%0,%1,%2,%3};" \
    : "+f"((acc)[0]), "+f"((acc)[1]), "+f"((acc)[2]), "+f"((acc)[3]) \
    : "r"((A)[0]), "r"((A)[1]), "r"((A)[2]), "r"((A)[3]), "r"((B)[0]), "r"((B)[1]))

// stage one 16-k sub-chunk (64 rows, hi+lo) into this warp's private ring buffer
__device__ __forceinline__ void stage_sub(const bf16* sH, const bf16* sL, int kk,
                                          uint32_t db, int srow, int shalf)
{
#pragma unroll
    for (int a2 = 0; a2 < 4; ++a2) {
        int rr = a2 * 16 + srow;
        uint32_t d = db + rr * 80 + shalf * 16;
        const bf16* ph = sH + rr * 512 + kk + shalf * 8;
        const bf16* pl = sL + rr * 512 + kk + shalf * 8;
        asm volatile("cp.async.cg.shared.global [%0],[%1],16;\n\t"
                     "cp.async.cg.shared.global [%2],[%3],16;"
                     :: "r"(d), "l"(ph), "r"(d + 32), "l"(pl) : "memory");
    }
    asm volatile("cp.async.commit_group;" ::: "memory");
}

__global__ void __launch_bounds__(NTH, 1)
gru_scan_kernel(const void* __restrict__ resets,
                const float* __restrict__ Wi, const float* __restrict__ bi,
                const float* __restrict__ Wh, const float* __restrict__ bhn,
                float* __restrict__ out)
{
    extern __shared__ char smem[];
    const uint32_t sbase = smem_u32(smem);
    float* rm   = (float*)(smem + SM_RM);
    float* bia  = (float*)(smem + SM_BIA);
    float* bhna = (float*)(smem + SM_BHN);
    float* part = (float*)(smem + SM_PART);

    const int tid = threadIdx.x, lane = tid & 31, warp = tid >> 5;  // warp 0..7 = K-slice
    const int cta = blockIdx.x, group = cta >> 6, lyr = group ? 0 : 1;
    const int gwBase = (cta & 63) * 8;
    const int rmode = g_reset_mode;
    const int r8 = lane & 7, g4 = lane >> 3;

    // ---- init: weights (bf16 hi/lo) into staging smem: rows (k>>6)*24+c x 144B ----
    const float* WiL = Wi + (size_t)lyr * WW * W3;
    const float* WhL = Wh + (size_t)lyr * WW * W3;
    for (int idx = tid; idx < 24 * 1024; idx += NTH) {
        int c = idx % 24, k = idx / 24;
        int gc = gwBase + (c & 7) + (c >> 3) * WW;
        float v = (k < WW) ? WiL[(size_t)k * W3 + gc] : WhL[(size_t)(k - WW) * W3 + gc];
        bf16 h = __float2bfloat16(v);
        bf16 l = __float2bfloat16(v - __bfloat162float(h));
        int off = ((k >> 6) * 24 + c) * 144 + (k & 63) * 2;
        *(bf16*)(smem + SM_WSTG + off) = h;
        *(bf16*)(smem + SM_WSTG + 55296 + off) = l;
    }
    if (tid < 24) bia[tid] = bi[lyr * W3 + (tid >> 3) * WW + gwBase + (tid & 7)];
    if (tid < 8)  bhna[tid] = bhn[lyr * WW + gwBase + tid];
    unsigned gen = 0;
    if (tid == 0) gen = g_gen;
    __syncthreads();

    // ---- load persistent B fragments (hi/lo) for this warp's K=128 slice ----
    uint32_t bfr[3][8][2][2];
#pragma unroll
    for (int nt = 0; nt < 3; ++nt)
#pragma unroll
        for (int j = 0; j < 8; ++j) {
            int kc = warp * 2 + (j >> 2), q = j & 3;
            uint32_t ba = sbase + SM_WSTG + kc * 3456 +
                          (nt * 8 + r8) * 144 + (g4 & 1) * 16 + q * 32;
            LDSM2(bfr[nt][j][0], ba);
            LDSM2(bfr[nt][j][1], ba + 55296);
        }
    __syncthreads();   // weight staging area now reusable as A/part

    const uint32_t awb = sbase + SM_A + warp * 20480;   // 4 bufs x 5120
    const uint32_t aoff = ((g4 & 1) * 8 + r8) * 80 + (g4 >> 1) * 16;
    const int k0 = (warp & 3) * 128;                    // k base within half
    const int srow = lane >> 1, shalf = lane & 1;

    float* out_carry = out;
    float* out_ys    = out + 2 * BB * WW;
    bool pre = false;

#pragma unroll 1
    for (int p = 0; p <= TT; ++p) {
        const bool active = group ? (p < TT) : (p >= 1);
        const int t = group ? p : (p - 1);
        const int hbuf = (p - 1) & 1;
        bool preN = false;
        float hpe0 = 0.0f, hpe1 = 0.0f;
        if (active) {
            const bool zeroH = group ? (p == 0) : (p == 1);
            const bf16* iHi = group ? &g_xHi[t][0][0] : &g_hHi[0][hbuf][0][0];
            const bf16* iLo = group ? &g_xLo[t][0][0] : &g_hLo[0][hbuf][0][0];
            const bf16* sH = (warp < 4) ? iHi : &g_hHi[lyr][hbuf][0][0];
            const bf16* sL = (warp < 4) ? iLo : &g_hLo[lyr][hbuf][0][0];

            if (tid < BB)
                rm[tid] = zeroH ? 0.0f : reset_mask(resets, rmode, t * BB + tid);

            // early hp prefetch: epilogue values, issued now to hide L2 latency
            {
                const float* hFe = &g_hF[lyr][hbuf][0][0];
                const int be = tid >> 3, we = gwBase + (tid & 7);
                hpe0 = __ldcg(hFe + be * 512 + we);
                hpe1 = __ldcg(hFe + (be + 32) * 512 + we);
            }

            // one CTA prefetches the next timestep's ins slab (128 KB) into L2
            if (cta == 64 && p + 1 < TT) {
                const char* nb = (const char*)&g_xHi[p + 1][0][0];
                const char* nl = (const char*)&g_xLo[p + 1][0][0];
                asm volatile("prefetch.global.L2 [%0];" :: "l"(nb + tid * 256));
                asm volatile("prefetch.global.L2 [%0];" :: "l"(nb + tid * 256 + 128));
                asm volatile("prefetch.global.L2 [%0];" :: "l"(nl + tid * 256));
                asm volatile("prefetch.global.L2 [%0];" :: "l"(nl + tid * 256 + 128));
            }

            float acc[4][3][4];
#pragma unroll
            for (int mt = 0; mt < 4; ++mt)
#pragma unroll
                for (int nt = 0; nt < 3; ++nt)
#pragma unroll
                    for (int q = 0; q < 4; ++q) acc[mt][nt][q] = 0.0f;

            if (!pre) {
                stage_sub(sH, sL, k0 + 0 * 16, awb + 0 * 5120, srow, shalf);
                stage_sub(sH, sL, k0 + 1 * 16, awb + 1 * 5120, srow, shalf);
                stage_sub(sH, sL, k0 + 2 * 16, awb + 2 * 5120, srow, shalf);
            }

#pragma unroll
            for (int s = 0; s < 8; ++s) {
                if (s < 6)       asm volatile("cp.async.wait_group 2;" ::: "memory");
                else if (s == 6) asm volatile("cp.async.wait_group 1;" ::: "memory");
                else             asm volatile("cp.async.wait_group 0;" ::: "memory");
                __syncwarp();
                const uint32_t ab = awb + (s & 3) * 5120 + aoff;
#pragma unroll
                for (int mt = 0; mt < 4; ++mt) {
                    uint32_t ah[4], al[4];
                    LDSM4(ah, ab + mt * 1280);
                    LDSM4(al, ab + mt * 1280 + 32);
#pragma unroll
                    for (int nt = 0; nt < 3; ++nt) {
                        MMA(acc[mt][nt], ah, bfr[nt][s][0]);
                        MMA(acc[mt][nt], ah, bfr[nt][s][1]);
                        MMA(acc[mt][nt], al, bfr[nt][s][0]);
                    }
                }
                if (s < 5)
                    stage_sub(sH, sL, k0 + (s + 3) * 16, awb + ((s + 3) & 3) * 5120,
                              srow, shalf);
            }

            // dump this warp's 64x24 partial tile
            {
                float* prt = part + warp * 1536;
                const int dr = lane >> 2, dc = (lane & 3) * 2;
#pragma unroll
                for (int mt = 0; mt < 4; ++mt)
#pragma unroll
                    for (int nt = 0; nt < 3; ++nt) {
                        int b0 = (mt * 16 + dr) * 24 + nt * 8 + dc;
                        *(float2*)(prt + b0)       = make_float2(acc[mt][nt][0], acc[mt][nt][1]);
                        *(float2*)(prt + b0 + 192) = make_float2(acc[mt][nt][2], acc[mt][nt][3]);
                    }
            }

            // group1 input warps prestage next phase's (static) x sub-chunks
            if (group == 1 && warp < 4 && p + 1 < TT) {
                const bf16* nH = &g_xHi[p + 1][0][0];
                const bf16* nL = &g_xLo[p + 1][0][0];
                stage_sub(nH, nL, k0 + 0 * 16, awb + 0 * 5120, srow, shalf);
                stage_sub(nH, nL, k0 + 1 * 16, awb + 1 * 5120, srow, shalf);
                stage_sub(nH, nL, k0 + 2 * 16, awb + 2 * 5120, srow, shalf);
                preN = true;
            }
        }

        __syncthreads();

        if (active) {
#pragma unroll
            for (int e = 0; e < 2; ++e) {
                const int idx = tid + e * 256;
                const int b = idx >> 3, ttl = idx & 7;
                const float m = rm[b];
                float si[3], sh[3];
#pragma unroll
                for (int g = 0; g < 3; ++g) {
                    const int c = g * 8 + ttl;
                    float a0 = 0.0f, a1 = 0.0f;
#pragma unroll
                    for (int w8 = 0; w8 < 4; ++w8) {
                        a0 += part[w8 * 1536 + b * 24 + c];
                        a1 += part[(w8 + 4) * 1536 + b * 24 + c];
                    }
                    si[g] = a0; sh[g] = a1;
                }
                const float r = 1.0f / (1.0f + __expf(-(bia[ttl] + si[0] + m * sh[0])));
                const float z = 1.0f / (1.0f + __expf(-(bia[8 + ttl] + si[1] + m * sh[1])));
                const float n = tanhf(bia[16 + ttl] + si[2] + r * (m * sh[2] + bhna[ttl]));
                const int w = gwBase + ttl;
                const float hp = m * (e ? hpe1 : hpe0);
                const float h = (1.0f - z) * n + z * hp;
                bf16 hh = __float2bfloat16(h);
                const int pb = p & 1;
                g_hF [lyr][pb][b][w] = h;
                g_hHi[lyr][pb][b][w] = hh;
                g_hLo[lyr][pb][b][w] = __float2bfloat16(h - __bfloat162float(hh));
                if (group == 0) {
                    out_ys[(size_t)t * BB * WW + b * WW + w] = h;
                    if (p == TT) out_carry[BB * WW + b * WW + w] = h;
                } else if (p == TT - 1) {
                    out_carry[b * WW + w] = h;
                }
            }
        }

        // lockstep grid barrier
        __syncthreads();
        if (tid == 0) {
            __threadfence();
            unsigned a = atomicAdd(&g_cnt, 1);
            gen += 1;
            if (a == GRID - 1) {
                g_cnt = 0;
                __threadfence();
                g_gen = gen;
            } else {
                while (g_gen < gen) { __nanosleep(20); }
                __threadfence();
            }
        }
        __syncthreads();
        pre = preN;
    }
}

extern "C" void kernel_launch(void* const* d_in, const int* in_sizes, int n_in,
                              void* d_out, int out_size)
{
    const float* ins    = (const float*)d_in[0];
    const void*  resets = (const void*)d_in[1];
    const float* Wi     = (const float*)d_in[2];
    const float* bi     = (const float*)d_in[3];
    const float* Wh     = (const float*)d_in[4];
    const float* bhn    = (const float*)d_in[5];
    float*       out    = (float*)d_out;

    prep_kernel<<<32769, 256>>>(ins, (const unsigned*)resets);

    cudaFuncSetAttribute(gru_scan_kernel,
                         cudaFuncAttributeMaxDynamicSharedMemorySize, SMEM_BYTES);
    gru_scan_kernel<<<GRID, NTH, SMEM_BYTES>>>(resets, Wi, bi, Wh, bhn, out);
}

// round 16
// speedup vs baseline: 2.1092x; 1.7057x over previous
#include <cuda_runtime.h>
#include <cuda_fp16.h>
#include <cstdint>

#define TT 1024
#define BB 64
#define WW 512
#define W3 1536
#define GRID 128
#define NTH 256

// smem layout (bytes)
#define SM_RM   0
#define SM_BIA  256
#define SM_BHN  384
#define SM_WSTG 1024                 // weight staging fp16 (55296B), init-only
#define SM_PART 1024                 // 8 x 64 x 24 fp32 = 49152 -> ends 50176
#define SM_A    50176                // 8 warps x 4 pair-bufs x 5120B = 163840
#define SMEM_BYTES 214016

__device__ __align__(128) __half g_x[TT][BB][WW];      // ins as fp16
__device__ __align__(128) __half g_h[2][2][BB][WW];    // [layer][buf][b][w] fp16
__device__ __align__(128) float  g_hF[2][2][BB][WW];   // fp32 h for hp term
__device__ unsigned g_cnt = 0;
__device__ volatile unsigned g_gen = 0;
__device__ int g_reset_mode = 0;

__device__ __forceinline__ float reset_mask(const void* r, int mode, int idx)
{
    if (mode == 1) return ((const int*)r)[idx] != 0 ? 0.0f : 1.0f;
    if (mode == 2) return ((const float*)r)[idx] != 0.0f ? 0.0f : 1.0f;
    return ((const unsigned char*)r)[idx] != 0 ? 0.0f : 1.0f;
}

// prep: convert ins to fp16 (blocks 0..32767); block 32768 sniffs reset dtype
__global__ void prep_kernel(const float* __restrict__ ins,
                            const unsigned* __restrict__ resets)
{
    if (blockIdx.x == 32768) {
        __shared__ unsigned red[256];
        unsigned m = 0;
        for (int i = threadIdx.x; i < (TT * BB) / 4; i += 256) m = max(m, resets[i]);
        red[threadIdx.x] = m;
        __syncthreads();
        for (int s = 128; s > 0; s >>= 1) {
            if (threadIdx.x < s) red[threadIdx.x] = max(red[threadIdx.x], red[threadIdx.x + s]);
            __syncthreads();
        }
        if (threadIdx.x == 0) {
            unsigned mx = red[0];
            g_reset_mode = (mx <= 1u) ? 1 : (mx >= 0x10000000u ? 2 : 0);
        }
        return;
    }
    size_t i = ((size_t)blockIdx.x * 256 + threadIdx.x) * 4;
    float4 v = *(const float4*)(ins + i);
    __half* x = &g_x[0][0][0];
    x[i + 0] = __float2half_rn(v.x);
    x[i + 1] = __float2half_rn(v.y);
    x[i + 2] = __float2half_rn(v.z);
    x[i + 3] = __float2half_rn(v.w);
}

__device__ __forceinline__ uint32_t smem_u32(const void* p)
{
    uint32_t a;
    asm("{ .reg .u64 t; cvta.to.shared.u64 t, %1; cvt.u32.u64 %0, t; }" : "=r"(a) : "l"(p));
    return a;
}

#define LDSM4(d, addr) asm volatile( \
    "ldmatrix.sync.aligned.m8n8.x4.shared.b16 {%0,%1,%2,%3},[%4];" \
    : "=r"((d)[0]), "=r"((d)[1]), "=r"((d)[2]), "=r"((d)[3]) : "r"(addr))
#define LDSM2(d, addr) asm volatile( \
    "ldmatrix.sync.aligned.m8n8.x2.shared.b16 {%0,%1},[%2];" \
    : "=r"((d)[0]), "=r"((d)[1]) : "r"(addr))
#define MMA(acc, A, B) asm volatile( \
    "mma.sync.aligned.m16n8k16.row.col.f32.f16.f16.f32 " \
    "{%0,%1,%2,%3},{%4,%5,%6,%7},{%8,%9},{%0,%1,%2,%3};" \
    : "+f"((acc)[0]), "+f"((acc)[1]), "+f"((acc)[2]), "+f"((acc)[3]) \
    : "r"((A)[0]), "r"((A)[1]), "r"((A)[2]), "r"((A)[3]), "r"((B)[0]), "r"((B)[1]))

// stage one 32-k pair (64 rows x 64B) into a 5120B pair-buffer (80B row stride)
__device__ __forceinline__ void stage_pair(const __half* src, int kpair,
                                           uint32_t db, int lane)
{
#pragma unroll
    for (int i = 0; i < 8; ++i) {
        int c = lane + 32 * i;
        int row = c >> 2, ch = c & 3;
        uint32_t d = db + row * 80 + ch * 16;
        const __half* s = src + row * 512 + kpair + ch * 8;
        asm volatile("cp.async.cg.shared.global [%0],[%1],16;" :: "r"(d), "l"(s) : "memory");
    }
    asm volatile("cp.async.commit_group;" ::: "memory");
}

__global__ void __launch_bounds__(NTH, 1)
gru_scan_kernel(const void* __restrict__ resets,
                const float* __restrict__ Wi, const float* __restrict__ bi,
                const float* __restrict__ Wh, const float* __restrict__ bhn,
                float* __restrict__ out)
{
    extern __shared__ char smem[];
    const uint32_t sbase = smem_u32(smem);
    float* rm   = (float*)(smem + SM_RM);
    float* bia  = (float*)(smem + SM_BIA);
    float* bhna = (float*)(smem + SM_BHN);
    float* part = (float*)(smem + SM_PART);

    const int tid = threadIdx.x, lane = tid & 31, warp = tid >> 5;  // warp 0..7 = K-slice
    const int cta = blockIdx.x, group = cta >> 6, lyr = group ? 0 : 1;
    const int gwBase = (cta & 63) * 8;
    const int rmode = g_reset_mode;
    const int r8 = lane & 7, g4 = lane >> 3;

    // ---- init: weights (fp16) into staging smem: rows (k>>6)*24+c x 144B ----
    const float* WiL = Wi + (size_t)lyr * WW * W3;
    const float* WhL = Wh + (size_t)lyr * WW * W3;
    for (int idx = tid; idx < 24 * 1024; idx += NTH) {
        int c = idx % 24, k = idx / 24;
        int gc = gwBase + (c & 7) + (c >> 3) * WW;
        float v = (k < WW) ? WiL[(size_t)k * W3 + gc] : WhL[(size_t)(k - WW) * W3 + gc];
        int off = ((k >> 6) * 24 + c) * 144 + (k & 63) * 2;
        *(__half*)(smem + SM_WSTG + off) = __float2half_rn(v);
    }
    if (tid < 24) bia[tid] = bi[lyr * W3 + (tid >> 3) * WW + gwBase + (tid & 7)];
    if (tid < 8)  bhna[tid] = bhn[lyr * WW + gwBase + tid];
    unsigned gen = 0;
    if (tid == 0) gen = g_gen;
    __syncthreads();

    // ---- persistent B fragments for this warp's K=128 slice (fp16, 48 regs) ----
    uint32_t bfr[3][8][2];
#pragma unroll
    for (int nt = 0; nt < 3; ++nt)
#pragma unroll
        for (int j = 0; j < 8; ++j) {
            int kc = warp * 2 + (j >> 2), q = j & 3;
            uint32_t ba = sbase + SM_WSTG + kc * 3456 +
                          (nt * 8 + r8) * 144 + (g4 & 1) * 16 + q * 32;
            LDSM2(bfr[nt][j], ba);
        }
    __syncthreads();   // weight staging area now reusable as A ring

    const uint32_t awb = sbase + SM_A + warp * 20480;   // 4 pair-bufs x 5120
    const int k0 = (warp & 3) * 128;                    // k base within half

    float* out_carry = out;
    float* out_ys    = out + 2 * BB * WW;
    bool pre = false;

#pragma unroll 1
    for (int p = 0; p <= TT; ++p) {
        const bool active = group ? (p < TT) : (p >= 1);
        const int t = group ? p : (p - 1);
        const int hbuf = (p - 1) & 1;
        bool preN = false;
        float hpe0 = 0.0f, hpe1 = 0.0f;
        if (active) {
            const bool zeroH = group ? (p == 0) : (p == 1);
            const __half* iA = group ? &g_x[t][0][0] : &g_h[0][hbuf][0][0];
            const __half* sA = (warp < 4) ? iA : &g_h[lyr][hbuf][0][0];

            if (tid < BB)
                rm[tid] = zeroH ? 0.0f : reset_mask(resets, rmode, t * BB + tid);

            // early hp prefetch (hides epilogue L2 latency)
            {
                const float* hFe = &g_hF[lyr][hbuf][0][0];
                const int be = tid >> 3, we = gwBase + (tid & 7);
                hpe0 = __ldcg(hFe + be * 512 + we);
                hpe1 = __ldcg(hFe + (be + 32) * 512 + we);
            }

            // one CTA prefetches the next timestep's x slab (64 KB) into L2
            if (cta == 64 && p + 1 < TT) {
                const char* nb = (const char*)&g_x[p + 1][0][0];
                asm volatile("prefetch.global.L2 [%0];" :: "l"(nb + tid * 256));
                asm volatile("prefetch.global.L2 [%0];" :: "l"(nb + tid * 256 + 128));
            }

            // stage full K=128 slice (4 pairs) unless prestaged last phase
            if (!pre) {
#pragma unroll
                for (int pr = 0; pr < 4; ++pr)
                    stage_pair(sA, k0 + pr * 32, awb + pr * 5120, lane);
            }

            float acc[4][3][4];
#pragma unroll
            for (int mt = 0; mt < 4; ++mt)
#pragma unroll
                for (int nt = 0; nt < 3; ++nt)
#pragma unroll
                    for (int q = 0; q < 4; ++q) acc[mt][nt][q] = 0.0f;

            asm volatile("cp.async.wait_group 0;" ::: "memory");
            __syncwarp();

#pragma unroll
            for (int s = 0; s < 8; ++s) {
                const uint32_t ab = awb + (s >> 1) * 5120 + (s & 1) * 32 +
                                    (g4 >> 1) * 16;
#pragma unroll
                for (int mt = 0; mt < 4; ++mt) {
                    uint32_t ah[4];
                    LDSM4(ah, ab + (mt * 16 + r8 + (g4 & 1) * 8) * 80);
#pragma unroll
                    for (int nt = 0; nt < 3; ++nt)
                        MMA(acc[mt][nt], ah, bfr[nt][s]);
                }
            }

            // dump this warp's 64x24 partial tile
            {
                float* prt = part + warp * 1536;
                const int dr = lane >> 2, dc = (lane & 3) * 2;
#pragma unroll
                for (int mt = 0; mt < 4; ++mt)
#pragma unroll
                    for (int nt = 0; nt < 3; ++nt) {
                        int b0 = (mt * 16 + dr) * 24 + nt * 8 + dc;
                        *(float2*)(prt + b0)       = make_float2(acc[mt][nt][0], acc[mt][nt][1]);
                        *(float2*)(prt + b0 + 192) = make_float2(acc[mt][nt][2], acc[mt][nt][3]);
                    }
            }

            // group1 input warps prestage next phase's (static) x slice
            if (group == 1 && warp < 4 && p + 1 < TT) {
                const __half* nA = &g_x[p + 1][0][0];
#pragma unroll
                for (int pr = 0; pr < 4; ++pr)
                    stage_pair(nA, k0 + pr * 32, awb + pr * 5120, lane);
                preN = true;
            }
        }

        __syncthreads();

        if (active) {
#pragma unroll
            for (int e = 0; e < 2; ++e) {
                const int idx = tid + e * 256;
                const int b = idx >> 3, ttl = idx & 7;
                const float m = rm[b];
                float si[3], sh[3];
#pragma unroll
                for (int g = 0; g < 3; ++g) {
                    const int c = g * 8 + ttl;
                    float a0 = 0.0f, a1 = 0.0f;
#pragma unroll
                    for (int w8 = 0; w8 < 4; ++w8) {
                        a0 += part[w8 * 1536 + b * 24 + c];
                        a1 += part[(w8 + 4) * 1536 + b * 24 + c];
                    }
                    si[g] = a0; sh[g] = a1;
                }
                const float r = 1.0f / (1.0f + __expf(-(bia[ttl] + si[0] + m * sh[0])));
                const float z = 1.0f / (1.0f + __expf(-(bia[8 + ttl] + si[1] + m * sh[1])));
                const float n = tanhf(bia[16 + ttl] + si[2] + r * (m * sh[2] + bhna[ttl]));
                const int w = gwBase + ttl;
                const float hp = m * (e ? hpe1 : hpe0);
                const float h = (1.0f - z) * n + z * hp;
                const int pb = p & 1;
                g_hF[lyr][pb][b][w] = h;
                g_h [lyr][pb][b][w] = __float2half_rn(h);
                if (group == 0) {
                    out_ys[(size_t)t * BB * WW + b * WW + w] = h;
                    if (p == TT) out_carry[BB * WW + b * WW + w] = h;
                } else if (p == TT - 1) {
                    out_carry[b * WW + w] = h;
                }
            }
        }

        // lockstep grid barrier
        __syncthreads();
        if (tid == 0) {
            __threadfence();
            unsigned a = atomicAdd(&g_cnt, 1);
            gen += 1;
            if (a == GRID - 1) {
                g_cnt = 0;
                __threadfence();
                g_gen = gen;
            } else {
                while (g_gen < gen) { __nanosleep(20); }
                __threadfence();
            }
        }
        __syncthreads();
        pre = preN;
    }
}

extern "C" void kernel_launch(void* const* d_in, const int* in_sizes, int n_in,
                              void* d_out, int out_size)
{
    const float* ins    = (const float*)d_in[0];
    const void*  resets = (const void*)d_in[1];
    const float* Wi     = (const float*)d_in[2];
    const float* bi     = (const float*)d_in[3];
    const float* Wh     = (const float*)d_in[4];
    const float* bhn    = (const float*)d_in[5];
    float*       out    = (float*)d_out;

    prep_kernel<<<32769, 256>>>(ins, (const unsigned*)resets);

    cudaFuncSetAttribute(gru_scan_kernel,
                         cudaFuncAttributeMaxDynamicSharedMemorySize, SMEM_BYTES);
    gru_scan_kernel<<<GRID, NTH, SMEM_BYTES>>>(resets, Wi, bi, Wh, bhn, out);
}

// round 17
// speedup vs baseline: 2.3038x; 1.0923x over previous
#include <cuda_runtime.h>
#include <cuda_fp16.h>
#include <cstdint>

#define TT 1024
#define BB 64
#define WW 512
#define W3 1536
#define GRID 128
#define NTH 256

// smem layout (bytes)
#define SM_RM   0
#define SM_BIA  256
#define SM_BHN  384
#define SM_WSTG 1024                 // weight staging fp16 (55296B), init-only
#define SM_PART 1024                 // 8 x 64 x 24 fp32 = 49152 -> ends 50176
#define SM_A    50176                // 8 warps x 4 pair-bufs x 5120B = 163840
#define SMEM_BYTES 214016

__device__ __align__(128) __half g_x[TT][BB][WW];      // ins as fp16
__device__ __align__(128) __half g_h[2][2][BB][WW];    // [layer][buf][b][w] fp16
__device__ __align__(128) float  g_hF[2][2][BB][WW];   // fp32 h for hp term
__device__ unsigned g_cnt = 0;
__device__ unsigned g_gen = 0;
__device__ int g_reset_mode = 0;

__device__ __forceinline__ float reset_mask(const void* r, int mode, int idx)
{
    if (mode == 1) return ((const int*)r)[idx] != 0 ? 0.0f : 1.0f;
    if (mode == 2) return ((const float*)r)[idx] != 0.0f ? 0.0f : 1.0f;
    return ((const unsigned char*)r)[idx] != 0 ? 0.0f : 1.0f;
}

// prep: convert ins to fp16 (blocks 0..32767); block 32768 sniffs reset dtype
__global__ void prep_kernel(const float* __restrict__ ins,
                            const unsigned* __restrict__ resets)
{
    if (blockIdx.x == 32768) {
        __shared__ unsigned red[256];
        unsigned m = 0;
        for (int i = threadIdx.x; i < (TT * BB) / 4; i += 256) m = max(m, resets[i]);
        red[threadIdx.x] = m;
        __syncthreads();
        for (int s = 128; s > 0; s >>= 1) {
            if (threadIdx.x < s) red[threadIdx.x] = max(red[threadIdx.x], red[threadIdx.x + s]);
            __syncthreads();
        }
        if (threadIdx.x == 0) {
            unsigned mx = red[0];
            g_reset_mode = (mx <= 1u) ? 1 : (mx >= 0x10000000u ? 2 : 0);
        }
        return;
    }
    size_t i = ((size_t)blockIdx.x * 256 + threadIdx.x) * 4;
    float4 v = *(const float4*)(ins + i);
    __half* x = &g_x[0][0][0];
    x[i + 0] = __float2half_rn(v.x);
    x[i + 1] = __float2half_rn(v.y);
    x[i + 2] = __float2half_rn(v.z);
    x[i + 3] = __float2half_rn(v.w);
}

__device__ __forceinline__ uint32_t smem_u32(const void* p)
{
    uint32_t a;
    asm("{ .reg .u64 t; cvta.to.shared.u64 t, %1; cvt.u32.u64 %0, t; }" : "=r"(a) : "l"(p));
    return a;
}

#define LDSM4(d, addr) asm volatile( \
    "ldmatrix.sync.aligned.m8n8.x4.shared.b16 {%0,%1,%2,%3},[%4];" \
    : "=r"((d)[0]), "=r"((d)[1]), "=r"((d)[2]), "=r"((d)[3]) : "r"(addr))
#define LDSM2(d, addr) asm volatile( \
    "ldmatrix.sync.aligned.m8n8.x2.shared.b16 {%0,%1},[%2];" \
    : "=r"((d)[0]), "=r"((d)[1]) : "r"(addr))
#define MMA(acc, A, B) asm volatile( \
    "mma.sync.aligned.m16n8k16.row.col.f32.f16.f16.f32 " \
    "{%0,%1,%2,%3},{%4,%5,%6,%7},{%8,%9},{%0,%1,%2,%3};" \
    : "+f"((acc)[0]), "+f"((acc)[1]), "+f"((acc)[2]), "+f"((acc)[3]) \
    : "r"((A)[0]), "r"((A)[1]), "r"((A)[2]), "r"((A)[3]), "r"((B)[0]), "r"((B)[1]))

// stage one 32-k pair (64 rows x 64B) into a 5120B pair-buffer (80B row stride)
__device__ __forceinline__ void stage_pair(const __half* src, int kpair,
                                           uint32_t db, int lane)
{
#pragma unroll
    for (int i = 0; i < 8; ++i) {
        int c = lane + 32 * i;
        int row = c >> 2, ch = c & 3;
        uint32_t d = db + row * 80 + ch * 16;
        const __half* s = src + row * 512 + kpair + ch * 8;
        asm volatile("cp.async.cg.shared.global [%0],[%1],16;" :: "r"(d), "l"(s) : "memory");
    }
    asm volatile("cp.async.commit_group;" ::: "memory");
}

__global__ void __launch_bounds__(NTH, 1)
gru_scan_kernel(const void* __restrict__ resets,
                const float* __restrict__ Wi, const float* __restrict__ bi,
                const float* __restrict__ Wh, const float* __restrict__ bhn,
                float* __restrict__ out)
{
    extern __shared__ char smem[];
    const uint32_t sbase = smem_u32(smem);
    float* rm   = (float*)(smem + SM_RM);
    float* bia  = (float*)(smem + SM_BIA);
    float* bhna = (float*)(smem + SM_BHN);
    float* part = (float*)(smem + SM_PART);

    const int tid = threadIdx.x, lane = tid & 31, warp = tid >> 5;  // warp 0..7 = K-slice
    const int cta = blockIdx.x, group = cta >> 6, lyr = group ? 0 : 1;
    const int gwBase = (cta & 63) * 8;
    const int rmode = g_reset_mode;
    const int r8 = lane & 7, g4 = lane >> 3;

    // ---- init: weights (fp16) into staging smem: rows (k>>6)*24+c x 144B ----
    const float* WiL = Wi + (size_t)lyr * WW * W3;
    const float* WhL = Wh + (size_t)lyr * WW * W3;
    for (int idx = tid; idx < 24 * 1024; idx += NTH) {
        int c = idx % 24, k = idx / 24;
        int gc = gwBase + (c & 7) + (c >> 3) * WW;
        float v = (k < WW) ? WiL[(size_t)k * W3 + gc] : WhL[(size_t)(k - WW) * W3 + gc];
        int off = ((k >> 6) * 24 + c) * 144 + (k & 63) * 2;
        *(__half*)(smem + SM_WSTG + off) = __float2half_rn(v);
    }
    if (tid < 24) bia[tid] = bi[lyr * W3 + (tid >> 3) * WW + gwBase + (tid & 7)];
    if (tid < 8)  bhna[tid] = bhn[lyr * WW + gwBase + tid];
    unsigned gen = 0;
    if (tid == 0) {
        asm volatile("ld.acquire.gpu.global.u32 %0, [%1];" : "=r"(gen) : "l"(&g_gen));
    }
    __syncthreads();

    // ---- persistent B fragments for this warp's K=128 slice (fp16, 48 regs) ----
    uint32_t bfr[3][8][2];
#pragma unroll
    for (int nt = 0; nt < 3; ++nt)
#pragma unroll
        for (int j = 0; j < 8; ++j) {
            int kc = warp * 2 + (j >> 2), q = j & 3;
            uint32_t ba = sbase + SM_WSTG + kc * 3456 +
                          (nt * 8 + r8) * 144 + (g4 & 1) * 16 + q * 32;
            LDSM2(bfr[nt][j], ba);
        }
    __syncthreads();   // weight staging area now reusable as A ring

    const uint32_t awb = sbase + SM_A + warp * 20480;   // 4 pair-bufs x 5120
    const int k0 = (warp & 3) * 128;                    // k base within half

    float* out_carry = out;
    float* out_ys    = out + 2 * BB * WW;
    bool pre = false;

#pragma unroll 1
    for (int p = 0; p <= TT; ++p) {
        const bool active = group ? (p < TT) : (p >= 1);
        const int t = group ? p : (p - 1);
        const int hbuf = (p - 1) & 1;
        bool preN = false;
        float hpe0 = 0.0f, hpe1 = 0.0f;
        if (active) {
            const bool zeroH = group ? (p == 0) : (p == 1);
            const __half* iA = group ? &g_x[t][0][0] : &g_h[0][hbuf][0][0];
            const __half* sA = (warp < 4) ? iA : &g_h[lyr][hbuf][0][0];

            // stage full K=128 slice (4 pairs) unless prestaged last phase
            if (!pre) {
#pragma unroll
                for (int pr = 0; pr < 4; ++pr)
                    stage_pair(sA, k0 + pr * 32, awb + pr * 5120, lane);
            }

            if (tid < BB)
                rm[tid] = zeroH ? 0.0f : reset_mask(resets, rmode, t * BB + tid);

            // early hp prefetch (hides epilogue L2 latency)
            {
                const float* hFe = &g_hF[lyr][hbuf][0][0];
                const int be = tid >> 3, we = gwBase + (tid & 7);
                hpe0 = __ldcg(hFe + be * 512 + we);
                hpe1 = __ldcg(hFe + (be + 32) * 512 + we);
            }

            // one CTA prefetches the next timestep's x slab (64 KB) into L2
            if (cta == 64 && p + 1 < TT) {
                const char* nb = (const char*)&g_x[p + 1][0][0];
                asm volatile("prefetch.global.L2 [%0];" :: "l"(nb + tid * 256));
                asm volatile("prefetch.global.L2 [%0];" :: "l"(nb + tid * 256 + 128));
            }

            float acc[4][3][4];
#pragma unroll
            for (int mt = 0; mt < 4; ++mt)
#pragma unroll
                for (int nt = 0; nt < 3; ++nt)
#pragma unroll
                    for (int q = 0; q < 4; ++q) acc[mt][nt][q] = 0.0f;

            // compute with incremental arrival waits: pair (s>>1) arrives by step s
#pragma unroll
            for (int s = 0; s < 8; ++s) {
                if (s == 0) { asm volatile("cp.async.wait_group 3;" ::: "memory"); __syncwarp(); }
                if (s == 2) { asm volatile("cp.async.wait_group 2;" ::: "memory"); __syncwarp(); }
                if (s == 4) { asm volatile("cp.async.wait_group 1;" ::: "memory"); __syncwarp(); }
                if (s == 6) { asm volatile("cp.async.wait_group 0;" ::: "memory"); __syncwarp(); }
                const uint32_t ab = awb + (s >> 1) * 5120 + (s & 1) * 32 +
                                    (g4 >> 1) * 16;
#pragma unroll
                for (int mt = 0; mt < 4; ++mt) {
                    uint32_t ah[4];
                    LDSM4(ah, ab + (mt * 16 + r8 + (g4 & 1) * 8) * 80);
#pragma unroll
                    for (int nt = 0; nt < 3; ++nt)
                        MMA(acc[mt][nt], ah, bfr[nt][s]);
                }
            }

            // dump this warp's 64x24 partial tile
            {
                float* prt = part + warp * 1536;
                const int dr = lane >> 2, dc = (lane & 3) * 2;
#pragma unroll
                for (int mt = 0; mt < 4; ++mt)
#pragma unroll
                    for (int nt = 0; nt < 3; ++nt) {
                        int b0 = (mt * 16 + dr) * 24 + nt * 8 + dc;
                        *(float2*)(prt + b0)       = make_float2(acc[mt][nt][0], acc[mt][nt][1]);
                        *(float2*)(prt + b0 + 192) = make_float2(acc[mt][nt][2], acc[mt][nt][3]);
                    }
            }

            // group1 input warps prestage next phase's (static) x slice
            if (group == 1 && warp < 4 && p + 1 < TT) {
                const __half* nA = &g_x[p + 1][0][0];
#pragma unroll
                for (int pr = 0; pr < 4; ++pr)
                    stage_pair(nA, k0 + pr * 32, awb + pr * 5120, lane);
                preN = true;
            }
        }

        __syncthreads();

        if (active) {
#pragma unroll
            for (int e = 0; e < 2; ++e) {
                const int idx = tid + e * 256;
                const int b = idx >> 3, ttl = idx & 7;
                const float m = rm[b];
                float si[3], sh[3];
#pragma unroll
                for (int g = 0; g < 3; ++g) {
                    const int c = g * 8 + ttl;
                    float a0 = 0.0f, a1 = 0.0f;
#pragma unroll
                    for (int w8 = 0; w8 < 4; ++w8) {
                        a0 += part[w8 * 1536 + b * 24 + c];
                        a1 += part[(w8 + 4) * 1536 + b * 24 + c];
                    }
                    si[g] = a0; sh[g] = a1;
                }
                const float r = 1.0f / (1.0f + __expf(-(bia[ttl] + si[0] + m * sh[0])));
                const float z = 1.0f / (1.0f + __expf(-(bia[8 + ttl] + si[1] + m * sh[1])));
                const float n = tanhf(bia[16 + ttl] + si[2] + r * (m * sh[2] + bhna[ttl]));
                const int w = gwBase + ttl;
                const float hp = m * (e ? hpe1 : hpe0);
                const float h = (1.0f - z) * n + z * hp;
                const int pb = p & 1;
                g_hF[lyr][pb][b][w] = h;
                g_h [lyr][pb][b][w] = __float2half_rn(h);
                if (group == 0) {
                    out_ys[(size_t)t * BB * WW + b * WW + w] = h;
                    if (p == TT) out_carry[BB * WW + b * WW + w] = h;
                } else if (p == TT - 1) {
                    out_carry[b * WW + w] = h;
                }
            }
        }

        // lockstep grid barrier (release arrival / acquire poll)
        __syncthreads();
        if (tid == 0) {
            unsigned a;
            asm volatile("atom.add.release.gpu.global.u32 %0, [%1], 1;"
                         : "=r"(a) : "l"(&g_cnt) : "memory");
            gen += 1;
            if (a == GRID - 1) {
                asm volatile("st.relaxed.gpu.global.u32 [%0], 0;" :: "l"(&g_cnt) : "memory");
                asm volatile("st.release.gpu.global.u32 [%0], %1;"
                             :: "l"(&g_gen), "r"(gen) : "memory");
            } else {
                unsigned g;
                do {
                    asm volatile("ld.acquire.gpu.global.u32 %0, [%1];"
                                 : "=r"(g) : "l"(&g_gen) : "memory");
                    if (g < gen) __nanosleep(8);
                } while (g < gen);
            }
        }
        __syncthreads();
        pre = preN;
    }
}

extern "C" void kernel_launch(void* const* d_in, const int* in_sizes, int n_in,
                              void* d_out, int out_size)
{
    const float* ins    = (const float*)d_in[0];
    const void*  resets = (const void*)d_in[1];
    const float* Wi     = (const float*)d_in[2];
    const float* bi     = (const float*)d_in[3];
    const float* Wh     = (const float*)d_in[4];
    const float* bhn    = (const float*)d_in[5];
    float*       out    = (float*)d_out;

    prep_kernel<<<32769, 256>>>(ins, (const unsigned*)resets);

    cudaFuncSetAttribute(gru_scan_kernel,
                         cudaFuncAttributeMaxDynamicSharedMemorySize, SMEM_BYTES);
    gru_scan_kernel<<<GRID, NTH, SMEM_BYTES>>>(resets, Wi, bi, Wh, bhn, out);
}